// round 1
// baseline (speedup 1.0000x reference)
#include <cuda_runtime.h>
#include <math.h>

// Problem constants
#define B 8
#define N 2048
#define F 128
#define BN (B*N)

// ---------------- scratch (device globals; no allocation) ----------------
__device__ float g_Wh[BN * F];        // 8 MB
__device__ float g_s1[BN];
__device__ float g_s2[BN];
__device__ float g_s2s[BN];           // sorted s2 per batch (ascending)
__device__ int   g_perm[BN];          // sort permutation
__device__ float g_S[BN * F];         // suffix sums of w_j * Wh[perm[j],:]
__device__ float g_Z[B * (N + 1)];    // scalar suffix sums of w
__device__ float g_mean[B * F];       // uniform-mean fallback rows

// ---------------- Kernel 1: Wh = h @ W^T  (M=16384, 128x128) ----------------
__global__ void __launch_bounds__(256) gemm_kernel(const float* __restrict__ A,
                                                   const float* __restrict__ W) {
    __shared__ float As[64][33];
    __shared__ float Bs[32][68];
    const int m0 = blockIdx.x * 64;
    const int n0 = blockIdx.y * 64;
    const int tid = threadIdx.x;
    const int ty = tid >> 4;          // 0..15
    const int tx = tid & 15;          // 0..15

    float acc[4][4];
#pragma unroll
    for (int i = 0; i < 4; i++)
#pragma unroll
        for (int j = 0; j < 4; j++) acc[i][j] = 0.f;

    const int lr = tid >> 3;          // 0..31
    const int lk = (tid & 7) * 4;     // 0..28

    for (int k0 = 0; k0 < 128; k0 += 32) {
        // load A tile: 64 rows x 32 k
        float4 a0 = *(const float4*)(A + (size_t)(m0 + lr) * 128 + k0 + lk);
        float4 a1 = *(const float4*)(A + (size_t)(m0 + lr + 32) * 128 + k0 + lk);
        As[lr][lk + 0] = a0.x; As[lr][lk + 1] = a0.y; As[lr][lk + 2] = a0.z; As[lr][lk + 3] = a0.w;
        As[lr + 32][lk + 0] = a1.x; As[lr + 32][lk + 1] = a1.y; As[lr + 32][lk + 2] = a1.z; As[lr + 32][lk + 3] = a1.w;
        // load W tile transposed: Bs[k][n] = W[n0+n][k0+k]
        float4 w0 = *(const float4*)(W + (size_t)(n0 + lr) * 128 + k0 + lk);
        float4 w1 = *(const float4*)(W + (size_t)(n0 + lr + 32) * 128 + k0 + lk);
        Bs[lk + 0][lr] = w0.x; Bs[lk + 1][lr] = w0.y; Bs[lk + 2][lr] = w0.z; Bs[lk + 3][lr] = w0.w;
        Bs[lk + 0][lr + 32] = w1.x; Bs[lk + 1][lr + 32] = w1.y; Bs[lk + 2][lr + 32] = w1.z; Bs[lk + 3][lr + 32] = w1.w;
        __syncthreads();
#pragma unroll
        for (int kk = 0; kk < 32; kk++) {
            float af[4], bf[4];
#pragma unroll
            for (int i = 0; i < 4; i++) af[i] = As[ty * 4 + i][kk];
#pragma unroll
            for (int j = 0; j < 4; j++) bf[j] = Bs[kk][tx * 4 + j];
#pragma unroll
            for (int i = 0; i < 4; i++)
#pragma unroll
                for (int j = 0; j < 4; j++) acc[i][j] = fmaf(af[i], bf[j], acc[i][j]);
        }
        __syncthreads();
    }
#pragma unroll
    for (int i = 0; i < 4; i++) {
        float* crow = g_Wh + (size_t)(m0 + ty * 4 + i) * 128 + n0 + tx * 4;
#pragma unroll
        for (int j = 0; j < 4; j++) crow[j] = acc[i][j];
    }
}

// ---------------- Kernel 2: s1 = Wh.a1, s2 = Wh.a2 (warp per row) ----------------
__global__ void __launch_bounds__(256) s12_kernel(const float* __restrict__ a) {
    int warp = (blockIdx.x * blockDim.x + threadIdx.x) >> 5;
    int lane = threadIdx.x & 31;
    if (warp >= BN) return;
    const float* row = g_Wh + (size_t)warp * 128;
    float acc1 = 0.f, acc2 = 0.f;
#pragma unroll
    for (int f = 0; f < 128; f += 32) {
        float v = row[f + lane];
        acc1 = fmaf(v, a[f + lane], acc1);
        acc2 = fmaf(v, a[128 + f + lane], acc2);
    }
#pragma unroll
    for (int o = 16; o; o >>= 1) {
        acc1 += __shfl_down_sync(0xFFFFFFFFu, acc1, o);
        acc2 += __shfl_down_sync(0xFFFFFFFFu, acc2, o);
    }
    if (lane == 0) { g_s1[warp] = acc1; g_s2[warp] = acc2; }
}

// ---------------- Kernel 3: per-batch bitonic sort of s2 (ascending) ----------------
__global__ void __launch_bounds__(1024) sort_kernel() {
    __shared__ float key[2048];
    __shared__ int   idx[2048];
    const int b = blockIdx.x;
    const int t = threadIdx.x;
    key[t] = g_s2[b * N + t];             idx[t] = t;
    key[t + 1024] = g_s2[b * N + t + 1024]; idx[t + 1024] = t + 1024;
    __syncthreads();
    for (int k = 2; k <= 2048; k <<= 1) {
        for (int j = k >> 1; j > 0; j >>= 1) {
            int i = ((t & ~(j - 1)) << 1) | (t & (j - 1));
            int p = i | j;
            bool up = ((i & k) == 0);
            float ki = key[i], kp = key[p];
            bool sw = up ? (ki > kp) : (ki < kp);
            if (sw) {
                key[i] = kp; key[p] = ki;
                int ii = idx[i]; idx[i] = idx[p]; idx[p] = ii;
            }
            __syncthreads();
        }
    }
    g_s2s[b * N + t] = key[t];               g_perm[b * N + t] = idx[t];
    g_s2s[b * N + t + 1024] = key[t + 1024]; g_perm[b * N + t + 1024] = idx[t + 1024];
}

// ---------------- Kernel 4: per-batch weights + suffix scans ----------------
__global__ void __launch_bounds__(1024) scan_kernel() {
    __shared__ float w[2048];
    __shared__ float za[2048];
    __shared__ float zb[2048];
    __shared__ int   sp[2048];
    __shared__ float pw[8][128];
    __shared__ float pm[8][128];
    __shared__ float off[8][128];
    const int b = blockIdx.x;
    const int t = threadIdx.x;
    const float mx = g_s2s[b * N + 2047];
    w[t]        = expf(g_s2s[b * N + t] - mx);
    w[t + 1024] = expf(g_s2s[b * N + t + 1024] - mx);
    sp[t]        = g_perm[b * N + t];
    sp[t + 1024] = g_perm[b * N + t + 1024];
    za[t] = w[t]; za[t + 1024] = w[t + 1024];
    __syncthreads();

    // Hillis-Steele inclusive suffix scan of w -> Z
    float* src = za; float* dst = zb;
    for (int o = 1; o < 2048; o <<= 1) {
        dst[t]        = src[t] + ((t + o < 2048) ? src[t + o] : 0.f);
        dst[t + 1024] = src[t + 1024] + ((t + 1024 + o < 2048) ? src[t + 1024 + o] : 0.f);
        __syncthreads();
        float* tmp = src; src = dst; dst = tmp;
    }
    g_Z[b * (N + 1) + t] = src[t];
    g_Z[b * (N + 1) + t + 1024] = src[t + 1024];
    if (t == 0) g_Z[b * (N + 1) + 2048] = 0.f;

    // chunked suffix scan of w_j * Wh[perm[j], f] : 8 groups x 128 f
    const int g = t >> 7;
    const int f = t & 127;
    const float* Whb = g_Wh + (size_t)b * N * 128;
    const int j0 = g * 256;
    float accW = 0.f, accM = 0.f;
    for (int j = j0; j < j0 + 256; j++) {
        float x = Whb[(size_t)sp[j] * 128 + f];
        accW = fmaf(w[j], x, accW);
        accM += x;
    }
    pw[g][f] = accW; pm[g][f] = accM;
    __syncthreads();
    if (g == 0) {
        float o2 = 0.f;
        for (int gg = 7; gg >= 0; gg--) { off[gg][f] = o2; o2 += pw[gg][f]; }
        float m = 0.f;
        for (int gg = 0; gg < 8; gg++) m += pm[gg][f];
        g_mean[b * 128 + f] = m * (1.f / 2048.f);
    }
    __syncthreads();
    float acc = off[g][f];
    for (int j = j0 + 255; j >= j0; j--) {
        acc = fmaf(w[j], Whb[(size_t)sp[j] * 128 + f], acc);
        g_S[(size_t)(b * N + j) * 128 + f] = acc;
    }
}

// ---------------- Kernel 5: binary search + elu(S[k]/Z[k]) ----------------
__global__ void __launch_bounds__(128) out_kernel(float* __restrict__ out) {
    const int b = blockIdx.x >> 11;
    const int i = blockIdx.x & (N - 1);
    const int f = threadIdx.x;
    const float s1v = g_s1[b * N + i];
    const float* ss = g_s2s + b * N;
    // first k with s1v + ss[k] > 0 (monotone predicate; matches reference mask)
    int lo = 0, hi = N;
    while (lo < hi) {
        int mid = (lo + hi) >> 1;
        if (s1v + ss[mid] > 0.f) hi = mid; else lo = mid + 1;
    }
    float val;
    if (lo == N) {
        val = g_mean[b * 128 + f];              // all masked -> uniform softmax -> mean
    } else {
        val = g_S[(size_t)(b * N + lo) * 128 + f] / g_Z[b * (N + 1) + lo];
    }
    out[(size_t)(b * N + i) * 128 + f] = (val > 0.f) ? val : expm1f(val);
}

// ---------------- launch ----------------
extern "C" void kernel_launch(void* const* d_in, const int* in_sizes, int n_in,
                              void* d_out, int out_size) {
    const float* h = (const float*)d_in[0];   // [8,2048,128]
    const float* W = (const float*)d_in[1];   // [128,128]
    const float* a = (const float*)d_in[2];   // [256,1]
    // d_in[3] (A1), d_in[4] (A2) feed dead code in the reference: unused.
    float* out = (float*)d_out;

    dim3 gGrid(BN / 64, 2);
    gemm_kernel<<<gGrid, 256>>>(h, W);
    s12_kernel<<<(BN * 32) / 256, 256>>>(a);
    sort_kernel<<<B, 1024>>>();
    scan_kernel<<<B, 1024>>>();
    out_kernel<<<BN, 128>>>(out);
}

// round 3
// speedup vs baseline: 1.2748x; 1.2748x over previous
#include <cuda_runtime.h>
#include <math.h>

#define B 8
#define N 2048
#define F 128
#define BN (B*N)
#define G 32           // chunks per batch
#define C 64           // rows per chunk (G*C == N)

// ---------------- scratch (device globals) ----------------
__device__ float g_Wh[BN * F];          // 8 MB
__device__ float g_s1[BN];
__device__ float g_s2[BN];
__device__ float g_s2s[BN];             // sorted s2 per batch (ascending)
__device__ int   g_perm[BN];
__device__ float g_w[BN];               // exp(s2s - max) per batch
__device__ float g_S[BN * F];           // suffix sums of w_j * Wh[perm[j],:]
__device__ float g_Z[B * (N + 1)];      // scalar suffix sums of w
__device__ float g_mean[B * F];
__device__ float g_pw[B][G][F];         // chunk partial weighted sums
__device__ float g_pm[B][G][F];         // chunk partial plain sums (for mean)
__device__ float g_off[B][G][F];        // exclusive suffix offsets per chunk

// ---- Kernel 1: Wh = h @ W^T, 64x128 tile per block, fused s1/s2 epilogue ----
__global__ void __launch_bounds__(256) gemm_kernel(const float* __restrict__ A,
                                                   const float* __restrict__ W,
                                                   const float* __restrict__ a) {
    __shared__ float As[64][33];
    __shared__ float Bs[32][129];
    __shared__ float sa[256];
    const int m0 = blockIdx.x * 64;
    const int tid = threadIdx.x;
    sa[tid] = a[tid];

    const int ty = tid >> 4;          // 0..15, owns rows ty*4..+3
    const int tx = tid & 15;          // 0..15, owns cols tx*8..+7

    float acc[4][8];
#pragma unroll
    for (int i = 0; i < 4; i++)
#pragma unroll
        for (int j = 0; j < 8; j++) acc[i][j] = 0.f;

    const int lr = tid >> 3;          // 0..31
    const int lk = (tid & 7) * 4;     // 0..28

#pragma unroll
    for (int k0 = 0; k0 < 128; k0 += 32) {
        // A tile: 64 rows x 32 k
        float4 a0 = *(const float4*)(A + (size_t)(m0 + lr) * 128 + k0 + lk);
        float4 a1 = *(const float4*)(A + (size_t)(m0 + lr + 32) * 128 + k0 + lk);
        As[lr][lk + 0] = a0.x; As[lr][lk + 1] = a0.y; As[lr][lk + 2] = a0.z; As[lr][lk + 3] = a0.w;
        As[lr + 32][lk + 0] = a1.x; As[lr + 32][lk + 1] = a1.y; As[lr + 32][lk + 2] = a1.z; As[lr + 32][lk + 3] = a1.w;
        // W tile transposed: Bs[k][n] = W[n][k0+k], all 128 n
#pragma unroll
        for (int s = 0; s < 4; s++) {
            int slot = tid + s * 256;
            int n = slot >> 3;
            int kq = (slot & 7) * 4;
            float4 w4 = *(const float4*)(W + (size_t)n * 128 + k0 + kq);
            Bs[kq + 0][n] = w4.x; Bs[kq + 1][n] = w4.y; Bs[kq + 2][n] = w4.z; Bs[kq + 3][n] = w4.w;
        }
        __syncthreads();
#pragma unroll
        for (int kk = 0; kk < 32; kk++) {
            float af[4], bf[8];
#pragma unroll
            for (int i = 0; i < 4; i++) af[i] = As[ty * 4 + i][kk];
#pragma unroll
            for (int j = 0; j < 8; j++) bf[j] = Bs[kk][tx * 8 + j];
#pragma unroll
            for (int i = 0; i < 4; i++)
#pragma unroll
                for (int j = 0; j < 8; j++) acc[i][j] = fmaf(af[i], bf[j], acc[i][j]);
        }
        __syncthreads();
    }
#pragma unroll
    for (int i = 0; i < 4; i++) {
        const int m = m0 + ty * 4 + i;
        float* crow = g_Wh + (size_t)m * 128 + tx * 8;
        *(float4*)(crow + 0) = make_float4(acc[i][0], acc[i][1], acc[i][2], acc[i][3]);
        *(float4*)(crow + 4) = make_float4(acc[i][4], acc[i][5], acc[i][6], acc[i][7]);
        // fused s1/s2: dot with a1/a2, reduce across the 16 tx lanes
        float p1 = 0.f, p2 = 0.f;
#pragma unroll
        for (int j = 0; j < 8; j++) {
            p1 = fmaf(acc[i][j], sa[tx * 8 + j], p1);
            p2 = fmaf(acc[i][j], sa[128 + tx * 8 + j], p2);
        }
#pragma unroll
        for (int o = 8; o; o >>= 1) {
            p1 += __shfl_down_sync(0xFFFFFFFFu, p1, o, 16);
            p2 += __shfl_down_sync(0xFFFFFFFFu, p2, o, 16);
        }
        if (tx == 0) { g_s1[m] = p1; g_s2[m] = p2; }
    }
}

// ---- Kernel 2: per-batch bitonic sort of s2 + w=exp + scalar Z suffix ----
__global__ void __launch_bounds__(1024) sort_kernel() {
    __shared__ float key[2048];
    __shared__ int   idx[2048];
    __shared__ float alt[2048];
    const int b = blockIdx.x;
    const int t = threadIdx.x;
    key[t] = g_s2[b * N + t];               idx[t] = t;
    key[t + 1024] = g_s2[b * N + t + 1024]; idx[t + 1024] = t + 1024;
    __syncthreads();
    for (int k = 2; k <= 2048; k <<= 1) {
        for (int j = k >> 1; j > 0; j >>= 1) {
            int i = ((t & ~(j - 1)) << 1) | (t & (j - 1));
            int p = i | j;
            bool up = ((i & k) == 0);
            float ki = key[i], kp = key[p];
            bool sw = up ? (ki > kp) : (ki < kp);
            if (sw) {
                key[i] = kp; key[p] = ki;
                int ii = idx[i]; idx[i] = idx[p]; idx[p] = ii;
            }
            __syncthreads();
        }
    }
    g_s2s[b * N + t] = key[t];               g_perm[b * N + t] = idx[t];
    g_s2s[b * N + t + 1024] = key[t + 1024]; g_perm[b * N + t + 1024] = idx[t + 1024];

    // epilogue: w = exp(s2s - max), then Hillis-Steele inclusive suffix scan -> Z
    const float mx = key[2047];
    __syncthreads();
    float w0 = expf(key[t] - mx);
    float w1 = expf(key[t + 1024] - mx);
    g_w[b * N + t] = w0;
    g_w[b * N + t + 1024] = w1;
    key[t] = w0; key[t + 1024] = w1;
    __syncthreads();
    float* src = key; float* dst = alt;
    for (int o = 1; o < 2048; o <<= 1) {
        dst[t]        = src[t] + ((t + o < 2048) ? src[t + o] : 0.f);
        dst[t + 1024] = src[t + 1024] + ((t + 1024 + o < 2048) ? src[t + 1024 + o] : 0.f);
        __syncthreads();
        float* tmp = src; src = dst; dst = tmp;
    }
    g_Z[b * (N + 1) + t] = src[t];
    g_Z[b * (N + 1) + t + 1024] = src[t + 1024];
    if (t == 0) g_Z[b * (N + 1) + 2048] = 0.f;
}

// ---- Kernel 3: per-chunk partial sums (weighted + plain) ----
__global__ void __launch_bounds__(128) partial_kernel() {
    const int b = blockIdx.x >> 5;
    const int g = blockIdx.x & (G - 1);
    const int f = threadIdx.x;
    __shared__ float sw[C];
    __shared__ int   sp[C];
    if (f < C) {
        sw[f] = g_w[b * N + g * C + f];
        sp[f] = g_perm[b * N + g * C + f];
    }
    __syncthreads();
    const float* Whb = g_Wh + (size_t)b * N * 128;
    float accW = 0.f, accM = 0.f;
#pragma unroll 4
    for (int j = 0; j < C; j++) {
        float x = Whb[(size_t)sp[j] * 128 + f];
        accW = fmaf(sw[j], x, accW);
        accM += x;
    }
    g_pw[b][g][f] = accW;
    g_pm[b][g][f] = accM;
}

// ---- Kernel 4: per-batch chunk suffix offsets + mean ----
__global__ void __launch_bounds__(128) offsets_kernel() {
    const int b = blockIdx.x;
    const int f = threadIdx.x;
    float o2 = 0.f;
    for (int gg = G - 1; gg >= 0; gg--) {
        g_off[b][gg][f] = o2;
        o2 += g_pw[b][gg][f];
    }
    float m = 0.f;
    for (int gg = 0; gg < G; gg++) m += g_pm[b][gg][f];
    g_mean[b * 128 + f] = m * (1.f / 2048.f);
}

// ---- Kernel 5: per-chunk suffix scan writeback of S ----
__global__ void __launch_bounds__(128) scan2_kernel() {
    const int b = blockIdx.x >> 5;
    const int g = blockIdx.x & (G - 1);
    const int f = threadIdx.x;
    __shared__ float sw[C];
    __shared__ int   sp[C];
    if (f < C) {
        sw[f] = g_w[b * N + g * C + f];
        sp[f] = g_perm[b * N + g * C + f];
    }
    __syncthreads();
    const float* Whb = g_Wh + (size_t)b * N * 128;
    float* Sb = g_S + (size_t)(b * N + g * C) * 128;
    float acc = g_off[b][g][f];
#pragma unroll 4
    for (int j = C - 1; j >= 0; j--) {
        acc = fmaf(sw[j], Whb[(size_t)sp[j] * 128 + f], acc);
        Sb[(size_t)j * 128 + f] = acc;
    }
}

// ---- Kernel 6: binary search + elu(S[k]/Z[k]) ----
__global__ void __launch_bounds__(128) out_kernel(float* __restrict__ out) {
    const int b = blockIdx.x >> 11;
    const int i = blockIdx.x & (N - 1);
    const int f = threadIdx.x;
    const float s1v = g_s1[b * N + i];
    const float* ss = g_s2s + b * N;
    int lo = 0, hi = N;
    while (lo < hi) {
        int mid = (lo + hi) >> 1;
        if (s1v + ss[mid] > 0.f) hi = mid; else lo = mid + 1;
    }
    float val;
    if (lo == N) {
        val = g_mean[b * 128 + f];
    } else {
        val = g_S[(size_t)(b * N + lo) * 128 + f] / g_Z[b * (N + 1) + lo];
    }
    out[(size_t)(b * N + i) * 128 + f] = (val > 0.f) ? val : expm1f(val);
}

// ---------------- launch ----------------
extern "C" void kernel_launch(void* const* d_in, const int* in_sizes, int n_in,
                              void* d_out, int out_size) {
    const float* h = (const float*)d_in[0];   // [8,2048,128]
    const float* W = (const float*)d_in[1];   // [128,128]
    const float* a = (const float*)d_in[2];   // [256,1]
    float* out = (float*)d_out;

    gemm_kernel<<<BN / 64, 256>>>(h, W, a);
    sort_kernel<<<B, 1024>>>();
    partial_kernel<<<B * G, 128>>>();
    offsets_kernel<<<B, 128>>>();
    scan2_kernel<<<B * G, 128>>>();
    out_kernel<<<BN, 128>>>(out);
}

// round 4
// speedup vs baseline: 1.2840x; 1.0072x over previous
#include <cuda_runtime.h>
#include <math.h>

#define B 8
#define N 2048
#define F 128
#define BN (B*N)
#define G 32           // chunks per batch
#define C 64           // rows per chunk (G*C == N)

// ---------------- scratch (device globals) ----------------
__device__ float g_Wh[BN * F];          // 8 MB
__device__ float g_s1[BN];
__device__ float g_s2[BN];
__device__ float g_s2s[BN];             // sorted s2 per batch (ascending)
__device__ int   g_perm[BN];
__device__ float g_w[BN];               // exp(s2s - max) per batch
__device__ float g_S[BN * F];           // suffix sums of w_j * Wh[perm[j],:]
__device__ float g_Z[B * (N + 1)];      // scalar suffix sums of w
__device__ float g_mean[B * F];
__device__ float g_pw[B][G][F];         // chunk partial weighted sums
__device__ float g_pm[B][G][F];         // chunk partial plain sums (for mean)
__device__ int   g_flag[B * G];         // chunk-done flags (zeroed by sort_kernel)

// ---- Kernel 1: Wh = h @ W^T, 64x128 tile per block, fused s1/s2 epilogue ----
__global__ void __launch_bounds__(256) gemm_kernel(const float* __restrict__ A,
                                                   const float* __restrict__ W,
                                                   const float* __restrict__ a) {
    __shared__ float As[64][33];
    __shared__ float Bs[32][129];
    __shared__ float sa[256];
    const int m0 = blockIdx.x * 64;
    const int tid = threadIdx.x;
    sa[tid] = a[tid];

    const int ty = tid >> 4;          // 0..15, owns rows ty*4..+3
    const int tx = tid & 15;          // 0..15, owns cols tx*8..+7

    float acc[4][8];
#pragma unroll
    for (int i = 0; i < 4; i++)
#pragma unroll
        for (int j = 0; j < 8; j++) acc[i][j] = 0.f;

    const int lr = tid >> 3;          // 0..31
    const int lk = (tid & 7) * 4;     // 0..28

#pragma unroll
    for (int k0 = 0; k0 < 128; k0 += 32) {
        float4 a0 = *(const float4*)(A + (size_t)(m0 + lr) * 128 + k0 + lk);
        float4 a1 = *(const float4*)(A + (size_t)(m0 + lr + 32) * 128 + k0 + lk);
        As[lr][lk + 0] = a0.x; As[lr][lk + 1] = a0.y; As[lr][lk + 2] = a0.z; As[lr][lk + 3] = a0.w;
        As[lr + 32][lk + 0] = a1.x; As[lr + 32][lk + 1] = a1.y; As[lr + 32][lk + 2] = a1.z; As[lr + 32][lk + 3] = a1.w;
#pragma unroll
        for (int s = 0; s < 4; s++) {
            int slot = tid + s * 256;
            int n = slot >> 3;
            int kq = (slot & 7) * 4;
            float4 w4 = *(const float4*)(W + (size_t)n * 128 + k0 + kq);
            Bs[kq + 0][n] = w4.x; Bs[kq + 1][n] = w4.y; Bs[kq + 2][n] = w4.z; Bs[kq + 3][n] = w4.w;
        }
        __syncthreads();
#pragma unroll
        for (int kk = 0; kk < 32; kk++) {
            float af[4], bf[8];
#pragma unroll
            for (int i = 0; i < 4; i++) af[i] = As[ty * 4 + i][kk];
#pragma unroll
            for (int j = 0; j < 8; j++) bf[j] = Bs[kk][tx * 8 + j];
#pragma unroll
            for (int i = 0; i < 4; i++)
#pragma unroll
                for (int j = 0; j < 8; j++) acc[i][j] = fmaf(af[i], bf[j], acc[i][j]);
        }
        __syncthreads();
    }
#pragma unroll
    for (int i = 0; i < 4; i++) {
        const int m = m0 + ty * 4 + i;
        float* crow = g_Wh + (size_t)m * 128 + tx * 8;
        *(float4*)(crow + 0) = make_float4(acc[i][0], acc[i][1], acc[i][2], acc[i][3]);
        *(float4*)(crow + 4) = make_float4(acc[i][4], acc[i][5], acc[i][6], acc[i][7]);
        float p1 = 0.f, p2 = 0.f;
#pragma unroll
        for (int j = 0; j < 8; j++) {
            p1 = fmaf(acc[i][j], sa[tx * 8 + j], p1);
            p2 = fmaf(acc[i][j], sa[128 + tx * 8 + j], p2);
        }
#pragma unroll
        for (int o = 8; o; o >>= 1) {
            p1 += __shfl_down_sync(0xFFFFFFFFu, p1, o, 16);
            p2 += __shfl_down_sync(0xFFFFFFFFu, p2, o, 16);
        }
        if (tx == 0) { g_s1[m] = p1; g_s2[m] = p2; }
    }
}

// ---- Kernel 2: per-batch bitonic sort of s2 + w=exp + scalar Z suffix ----
// Also zeroes the lookback flags for the fused scan kernel (stream-ordered).
__global__ void __launch_bounds__(1024) sort_kernel() {
    __shared__ float key[2048];
    __shared__ int   idx[2048];
    __shared__ float alt[2048];
    const int b = blockIdx.x;
    const int t = threadIdx.x;
    if (t < G) g_flag[b * G + t] = 0;
    key[t] = g_s2[b * N + t];               idx[t] = t;
    key[t + 1024] = g_s2[b * N + t + 1024]; idx[t + 1024] = t + 1024;
    __syncthreads();
    for (int k = 2; k <= 2048; k <<= 1) {
        for (int j = k >> 1; j > 0; j >>= 1) {
            int i = ((t & ~(j - 1)) << 1) | (t & (j - 1));
            int p = i | j;
            bool up = ((i & k) == 0);
            float ki = key[i], kp = key[p];
            bool sw = up ? (ki > kp) : (ki < kp);
            if (sw) {
                key[i] = kp; key[p] = ki;
                int ii = idx[i]; idx[i] = idx[p]; idx[p] = ii;
            }
            __syncthreads();
        }
    }
    g_s2s[b * N + t] = key[t];               g_perm[b * N + t] = idx[t];
    g_s2s[b * N + t + 1024] = key[t + 1024]; g_perm[b * N + t + 1024] = idx[t + 1024];

    const float mx = key[2047];
    __syncthreads();
    float w0 = expf(key[t] - mx);
    float w1 = expf(key[t + 1024] - mx);
    g_w[b * N + t] = w0;
    g_w[b * N + t + 1024] = w1;
    key[t] = w0; key[t + 1024] = w1;
    __syncthreads();
    float* src = key; float* dst = alt;
    for (int o = 1; o < 2048; o <<= 1) {
        dst[t]        = src[t] + ((t + o < 2048) ? src[t + o] : 0.f);
        dst[t + 1024] = src[t + 1024] + ((t + 1024 + o < 2048) ? src[t + 1024 + o] : 0.f);
        __syncthreads();
        float* tmp = src; src = dst; dst = tmp;
    }
    g_Z[b * (N + 1) + t] = src[t];
    g_Z[b * (N + 1) + t + 1024] = src[t + 1024];
    if (t == 0) g_Z[b * (N + 1) + 2048] = 0.f;
}

// ---- Kernel 3: fused chunk partial + suffix lookback + suffix scan ----
// 256 co-resident blocks (128 thr, 32.5KB smem -> 7/SM; 148 SMs >> 256): spin is safe.
__global__ void __launch_bounds__(128) fused_scan_kernel() {
    const int b = blockIdx.x >> 5;
    const int g = blockIdx.x & (G - 1);
    const int f = threadIdx.x;
    __shared__ float rows[C][F];      // 32KB gather cache
    __shared__ float sw[C];
    __shared__ int   sp[C];
    if (f < C) {
        sw[f] = g_w[b * N + g * C + f];
        sp[f] = g_perm[b * N + g * C + f];
    }
    __syncthreads();
    const float* Whb = g_Wh + (size_t)b * N * 128;
    float accW = 0.f, accM = 0.f;
#pragma unroll 4
    for (int j = 0; j < C; j++) {
        float x = Whb[(size_t)sp[j] * 128 + f];
        rows[j][f] = x;
        accW = fmaf(sw[j], x, accW);
        accM += x;
    }
    g_pw[b][g][f] = accW;
    g_pm[b][g][f] = accM;
    __syncthreads();
    __threadfence();
    if (f == 0) {
        ((volatile int*)g_flag)[blockIdx.x] = 1;
        // acquire: wait for all higher chunks of this batch
        for (int gg = g + 1; gg < G; gg++)
            while (((volatile int*)g_flag)[(b << 5) | gg] == 0) {}
        if (g == 0)  // mean needs chunks 1..31 too (already covered above)
            ;
        __threadfence();
    }
    __syncthreads();
    float off = 0.f;
    for (int gg = g + 1; gg < G; gg++) off += g_pw[b][gg][f];
    float acc = off;
    float* Sb = g_S + (size_t)(b * N + g * C) * 128;
#pragma unroll 4
    for (int j = C - 1; j >= 0; j--) {
        acc = fmaf(sw[j], rows[j][f], acc);
        Sb[(size_t)j * 128 + f] = acc;
    }
    if (g == 0) {
        float m = accM;
        for (int gg = 1; gg < G; gg++) m += g_pm[b][gg][f];
        g_mean[b * 128 + f] = m * (1.f / 2048.f);
    }
}

// ---- Kernel 4: binary search + elu(S[k]/Z[k]) ----
__global__ void __launch_bounds__(128) out_kernel(float* __restrict__ out) {
    const int b = blockIdx.x >> 11;
    const int i = blockIdx.x & (N - 1);
    const int f = threadIdx.x;
    const float s1v = g_s1[b * N + i];
    const float* ss = g_s2s + b * N;
    int lo = 0, hi = N;
    while (lo < hi) {
        int mid = (lo + hi) >> 1;
        if (s1v + ss[mid] > 0.f) hi = mid; else lo = mid + 1;
    }
    float val;
    if (lo == N) {
        val = g_mean[b * 128 + f];
    } else {
        val = g_S[(size_t)(b * N + lo) * 128 + f] / g_Z[b * (N + 1) + lo];
    }
    out[(size_t)(b * N + i) * 128 + f] = (val > 0.f) ? val : expm1f(val);
}

// ---------------- launch ----------------
extern "C" void kernel_launch(void* const* d_in, const int* in_sizes, int n_in,
                              void* d_out, int out_size) {
    const float* h = (const float*)d_in[0];   // [8,2048,128]
    const float* W = (const float*)d_in[1];   // [128,128]
    const float* a = (const float*)d_in[2];   // [256,1]
    float* out = (float*)d_out;

    gemm_kernel<<<BN / 64, 256>>>(h, W, a);
    sort_kernel<<<B, 1024>>>();
    fused_scan_kernel<<<B * G, 128>>>();
    out_kernel<<<BN, 128>>>(out);
}

// round 5
// speedup vs baseline: 1.4497x; 1.1291x over previous
#include <cuda_runtime.h>
#include <math.h>

#define B 8
#define N 2048
#define F 128
#define BN (B*N)
#define G2 64          // chunks per batch (scan)
#define C2 32          // rows per chunk (G2*C2 == N)

// ---------------- scratch (device globals) ----------------
__device__ float g_Wh[BN * F];          // 8 MB
__device__ float g_s1[BN];
__device__ float g_s2[BN];
__device__ float g_s2s[BN];             // sorted s2 per batch (ascending)
__device__ int   g_perm[BN];
__device__ float g_w[BN];               // exp(s2s - max) per batch
__device__ float g_S[BN * F];           // suffix sums of w_j * Wh[perm[j],:]
__device__ float g_Z[B * (N + 1)];      // scalar suffix sums of w
__device__ float g_mean[B * F];
__device__ float g_pw[B][G2][F];        // chunk partial weighted sums
__device__ float g_pm[B][G2][F];        // chunk partial plain sums (for mean)
__device__ int   g_flag[B * G2];        // chunk-done flags (zeroed by sort_kernel)

// ---- Kernel 1: Wh = h @ W^T, 64x128 tile per block, fused s1/s2 epilogue ----
__global__ void __launch_bounds__(256) gemm_kernel(const float* __restrict__ A,
                                                   const float* __restrict__ W,
                                                   const float* __restrict__ a) {
    __shared__ float As[64][33];
    __shared__ float Bs[32][129];
    __shared__ float sa[256];
    const int m0 = blockIdx.x * 64;
    const int tid = threadIdx.x;
    sa[tid] = a[tid];

    const int ty = tid >> 4;
    const int tx = tid & 15;

    float acc[4][8];
#pragma unroll
    for (int i = 0; i < 4; i++)
#pragma unroll
        for (int j = 0; j < 8; j++) acc[i][j] = 0.f;

    const int lr = tid >> 3;
    const int lk = (tid & 7) * 4;

#pragma unroll
    for (int k0 = 0; k0 < 128; k0 += 32) {
        float4 a0 = *(const float4*)(A + (size_t)(m0 + lr) * 128 + k0 + lk);
        float4 a1 = *(const float4*)(A + (size_t)(m0 + lr + 32) * 128 + k0 + lk);
        As[lr][lk + 0] = a0.x; As[lr][lk + 1] = a0.y; As[lr][lk + 2] = a0.z; As[lr][lk + 3] = a0.w;
        As[lr + 32][lk + 0] = a1.x; As[lr + 32][lk + 1] = a1.y; As[lr + 32][lk + 2] = a1.z; As[lr + 32][lk + 3] = a1.w;
#pragma unroll
        for (int s = 0; s < 4; s++) {
            int slot = tid + s * 256;
            int n = slot >> 3;
            int kq = (slot & 7) * 4;
            float4 w4 = *(const float4*)(W + (size_t)n * 128 + k0 + kq);
            Bs[kq + 0][n] = w4.x; Bs[kq + 1][n] = w4.y; Bs[kq + 2][n] = w4.z; Bs[kq + 3][n] = w4.w;
        }
        __syncthreads();
#pragma unroll
        for (int kk = 0; kk < 32; kk++) {
            float af[4], bf[8];
#pragma unroll
            for (int i = 0; i < 4; i++) af[i] = As[ty * 4 + i][kk];
#pragma unroll
            for (int j = 0; j < 8; j++) bf[j] = Bs[kk][tx * 8 + j];
#pragma unroll
            for (int i = 0; i < 4; i++)
#pragma unroll
                for (int j = 0; j < 8; j++) acc[i][j] = fmaf(af[i], bf[j], acc[i][j]);
        }
        __syncthreads();
    }
#pragma unroll
    for (int i = 0; i < 4; i++) {
        const int m = m0 + ty * 4 + i;
        float* crow = g_Wh + (size_t)m * 128 + tx * 8;
        *(float4*)(crow + 0) = make_float4(acc[i][0], acc[i][1], acc[i][2], acc[i][3]);
        *(float4*)(crow + 4) = make_float4(acc[i][4], acc[i][5], acc[i][6], acc[i][7]);
        float p1 = 0.f, p2 = 0.f;
#pragma unroll
        for (int j = 0; j < 8; j++) {
            p1 = fmaf(acc[i][j], sa[tx * 8 + j], p1);
            p2 = fmaf(acc[i][j], sa[128 + tx * 8 + j], p2);
        }
#pragma unroll
        for (int o = 8; o; o >>= 1) {
            p1 += __shfl_down_sync(0xFFFFFFFFu, p1, o, 16);
            p2 += __shfl_down_sync(0xFFFFFFFFu, p2, o, 16);
        }
        if (tx == 0) { g_s1[m] = p1; g_s2[m] = p2; }
    }
}

// register-resident bitonic compare-exchange via warp shuffle (j <= 16)
__device__ __forceinline__ void bshuf(float& kv, int& iv, unsigned ei, int k, int j) {
    float pk = __shfl_xor_sync(0xFFFFFFFFu, kv, j);
    int   pi = __shfl_xor_sync(0xFFFFFFFFu, iv, j);
    bool lower = ((ei & (unsigned)j) == 0u);
    bool up    = ((ei & (unsigned)k) == 0u);
    float kl = lower ? kv : pk;
    float kh = lower ? pk : kv;
    bool sw = up ? (kl > kh) : (kl < kh);
    if (sw) { kv = pk; iv = pi; }
}

// ---- Kernel 2: per-batch bitonic sort of s2 (hybrid smem/warp) + w=exp + Z suffix ----
__global__ void __launch_bounds__(1024) sort_kernel() {
    __shared__ float key[2048];
    __shared__ int   idx[2048];
    __shared__ float alt[2048];
    const int b = blockIdx.x;
    const int t = threadIdx.x;
    if (t < B * G2 / B) g_flag[b * G2 + t] = 0;   // t < 64: zero this batch's flags

    // load into registers; phases k=2..32 are entirely intra-warp
    float k0 = g_s2[b * N + t];
    float k1 = g_s2[b * N + t + 1024];
    int   i0 = t, i1 = t + 1024;
#pragma unroll
    for (int k = 2; k <= 32; k <<= 1)
#pragma unroll
        for (int j = k >> 1; j; j >>= 1) {
            bshuf(k0, i0, (unsigned)t, k, j);
            bshuf(k1, i1, (unsigned)(t + 1024), k, j);
        }
    key[t] = k0; idx[t] = i0;
    key[t + 1024] = k1; idx[t + 1024] = i1;
    __syncthreads();

    for (int k = 64; k <= 2048; k <<= 1) {
        for (int j = k >> 1; j >= 32; j >>= 1) {
            int i = ((t & ~(j - 1)) << 1) | (t & (j - 1));
            int p = i | j;
            bool up = ((i & k) == 0);
            float ki = key[i], kp = key[p];
            bool sw = up ? (ki > kp) : (ki < kp);
            if (sw) {
                key[i] = kp; key[p] = ki;
                int ii = idx[i]; idx[i] = idx[p]; idx[p] = ii;
            }
            __syncthreads();
        }
        // tail j=16..1 in registers
        k0 = key[t]; i0 = idx[t];
        k1 = key[t + 1024]; i1 = idx[t + 1024];
#pragma unroll
        for (int j = 16; j; j >>= 1) {
            bshuf(k0, i0, (unsigned)t, k, j);
            bshuf(k1, i1, (unsigned)(t + 1024), k, j);
        }
        key[t] = k0; idx[t] = i0;
        key[t + 1024] = k1; idx[t + 1024] = i1;
        __syncthreads();
    }

    g_s2s[b * N + t] = key[t];               g_perm[b * N + t] = idx[t];
    g_s2s[b * N + t + 1024] = key[t + 1024]; g_perm[b * N + t + 1024] = idx[t + 1024];

    // epilogue: w = exp(s2s - max), then Hillis-Steele inclusive suffix scan -> Z
    const float mx = key[2047];
    __syncthreads();
    float w0 = expf(key[t] - mx);
    float w1 = expf(key[t + 1024] - mx);
    g_w[b * N + t] = w0;
    g_w[b * N + t + 1024] = w1;
    key[t] = w0; key[t + 1024] = w1;
    __syncthreads();
    float* src = key; float* dst = alt;
    for (int o = 1; o < 2048; o <<= 1) {
        dst[t]        = src[t] + ((t + o < 2048) ? src[t + o] : 0.f);
        dst[t + 1024] = src[t + 1024] + ((t + 1024 + o < 2048) ? src[t + 1024 + o] : 0.f);
        __syncthreads();
        float* tmp = src; src = dst; dst = tmp;
    }
    g_Z[b * (N + 1) + t] = src[t];
    g_Z[b * (N + 1) + t + 1024] = src[t + 1024];
    if (t == 0) g_Z[b * (N + 1) + 2048] = 0.f;
}

// ---- Kernel 3: fused chunk partial + suffix lookback + suffix scan (512 blocks) ----
__global__ void __launch_bounds__(128) fused_scan_kernel() {
    const int b = blockIdx.x >> 6;
    const int g = blockIdx.x & (G2 - 1);
    const int f = threadIdx.x;
    __shared__ float rows[C2][F];     // 16KB gather cache
    __shared__ float sw[C2];
    __shared__ int   sp[C2];
    if (f < C2) {
        sw[f] = g_w[b * N + g * C2 + f];
        sp[f] = g_perm[b * N + g * C2 + f];
    }
    __syncthreads();
    const float* Whb = g_Wh + (size_t)b * N * 128;
    float accW = 0.f, accM = 0.f;
#pragma unroll 4
    for (int j = 0; j < C2; j++) {
        float x = Whb[(size_t)sp[j] * 128 + f];
        rows[j][f] = x;
        accW = fmaf(sw[j], x, accW);
        accM += x;
    }
    g_pw[b][g][f] = accW;
    g_pm[b][g][f] = accM;
    __syncthreads();
    __threadfence();
    if (f == 0) {
        ((volatile int*)g_flag)[blockIdx.x] = 1;
        for (int gg = g + 1; gg < G2; gg++)
            while (((volatile int*)g_flag)[(b << 6) | gg] == 0) {}
        __threadfence();
    }
    __syncthreads();
    float off = 0.f;
    for (int gg = g + 1; gg < G2; gg++) off += __ldcg(&g_pw[b][gg][f]);
    float acc = off;
    float* Sb = g_S + (size_t)(b * N + g * C2) * 128;
#pragma unroll 4
    for (int j = C2 - 1; j >= 0; j--) {
        acc = fmaf(sw[j], rows[j][f], acc);
        Sb[(size_t)j * 128 + f] = acc;
    }
    if (g == 0) {
        float m = accM;
        for (int gg = 1; gg < G2; gg++) m += __ldcg(&g_pm[b][gg][f]);
        g_mean[b * 128 + f] = m * (1.f / 2048.f);
    }
}

// ---- Kernel 4: warp per row: lane-0 binary search + vectorized elu(S[k]/Z[k]) ----
__global__ void __launch_bounds__(256) out_kernel(float* __restrict__ out) {
    const int warp = threadIdx.x >> 5;
    const int lane = threadIdx.x & 31;
    const int row = blockIdx.x * 8 + warp;          // 0..16383
    const int b = row >> 11;
    const float* ss = g_s2s + b * N;
    int lo = 0;
    if (lane == 0) {
        const float s1v = g_s1[row];
        int hi = N;
        while (lo < hi) {
            int mid = (lo + hi) >> 1;
            if (s1v + ss[mid] > 0.f) hi = mid; else lo = mid + 1;
        }
    }
    lo = __shfl_sync(0xFFFFFFFFu, lo, 0);
    float4 v;
    if (lo == N) {
        v = ((const float4*)(g_mean + b * 128))[lane];
    } else {
        float invZ = 1.f / g_Z[b * (N + 1) + lo];
        float4 s = ((const float4*)(g_S + (size_t)(b * N + lo) * 128))[lane];
        v = make_float4(s.x * invZ, s.y * invZ, s.z * invZ, s.w * invZ);
    }
    v.x = (v.x > 0.f) ? v.x : expm1f(v.x);
    v.y = (v.y > 0.f) ? v.y : expm1f(v.y);
    v.z = (v.z > 0.f) ? v.z : expm1f(v.z);
    v.w = (v.w > 0.f) ? v.w : expm1f(v.w);
    ((float4*)(out + (size_t)row * 128))[lane] = v;
}

// ---------------- launch ----------------
extern "C" void kernel_launch(void* const* d_in, const int* in_sizes, int n_in,
                              void* d_out, int out_size) {
    const float* h = (const float*)d_in[0];   // [8,2048,128]
    const float* W = (const float*)d_in[1];   // [128,128]
    const float* a = (const float*)d_in[2];   // [256,1]
    float* out = (float*)d_out;

    gemm_kernel<<<BN / 64, 256>>>(h, W, a);
    sort_kernel<<<B, 1024>>>();
    fused_scan_kernel<<<B * G2, 128>>>();
    out_kernel<<<BN / 8, 256>>>(out);
}

// round 6
// speedup vs baseline: 1.4502x; 1.0004x over previous
#include <cuda_runtime.h>
#include <math.h>

#define B 8
#define N 2048
#define F 128
#define BN (B*N)
#define G2 64          // chunks per batch (scan)
#define C2 32          // rows per chunk (G2*C2 == N)

// ---------------- scratch (device globals) ----------------
__device__ float g_Wh[BN * F];          // 8 MB
__device__ float g_s1[BN];
__device__ float g_s2[BN];
__device__ float g_s2s[BN];             // sorted s2 per batch (ascending)
__device__ int   g_perm[BN];
__device__ float g_w[BN];               // exp(s2s - max) per batch
__device__ float g_S[BN * F];           // suffix sums of w_j * Wh[perm[j],:]
__device__ float g_Z[B * (N + 1)];      // scalar suffix sums of w
__device__ float g_mean[B * F];
__device__ float g_pw[B][G2][F];        // chunk partial weighted sums
__device__ float g_pm[B][G2][F];        // chunk partial plain sums (for mean)
__device__ int   g_flag[B * G2];        // chunk-done flags (zeroed by sort_kernel)

// ---- Kernel 1: Wh = h @ W^T, 64x128 tile per block, fused s1/s2 epilogue ----
__global__ void __launch_bounds__(256) gemm_kernel(const float* __restrict__ A,
                                                   const float* __restrict__ W,
                                                   const float* __restrict__ a) {
    __shared__ float As[64][33];
    __shared__ float Bs[32][129];
    __shared__ float sa[256];
    const int m0 = blockIdx.x * 64;
    const int tid = threadIdx.x;
    sa[tid] = a[tid];

    const int ty = tid >> 4;
    const int tx = tid & 15;

    float acc[4][8];
#pragma unroll
    for (int i = 0; i < 4; i++)
#pragma unroll
        for (int j = 0; j < 8; j++) acc[i][j] = 0.f;

    const int lr = tid >> 3;
    const int lk = (tid & 7) * 4;

#pragma unroll
    for (int k0 = 0; k0 < 128; k0 += 32) {
        float4 a0 = *(const float4*)(A + (size_t)(m0 + lr) * 128 + k0 + lk);
        float4 a1 = *(const float4*)(A + (size_t)(m0 + lr + 32) * 128 + k0 + lk);
        As[lr][lk + 0] = a0.x; As[lr][lk + 1] = a0.y; As[lr][lk + 2] = a0.z; As[lr][lk + 3] = a0.w;
        As[lr + 32][lk + 0] = a1.x; As[lr + 32][lk + 1] = a1.y; As[lr + 32][lk + 2] = a1.z; As[lr + 32][lk + 3] = a1.w;
#pragma unroll
        for (int s = 0; s < 4; s++) {
            int slot = tid + s * 256;
            int n = slot >> 3;
            int kq = (slot & 7) * 4;
            float4 w4 = *(const float4*)(W + (size_t)n * 128 + k0 + kq);
            Bs[kq + 0][n] = w4.x; Bs[kq + 1][n] = w4.y; Bs[kq + 2][n] = w4.z; Bs[kq + 3][n] = w4.w;
        }
        __syncthreads();
#pragma unroll
        for (int kk = 0; kk < 32; kk++) {
            float af[4], bf[8];
#pragma unroll
            for (int i = 0; i < 4; i++) af[i] = As[ty * 4 + i][kk];
#pragma unroll
            for (int j = 0; j < 8; j++) bf[j] = Bs[kk][tx * 8 + j];
#pragma unroll
            for (int i = 0; i < 4; i++)
#pragma unroll
                for (int j = 0; j < 8; j++) acc[i][j] = fmaf(af[i], bf[j], acc[i][j]);
        }
        __syncthreads();
    }
#pragma unroll
    for (int i = 0; i < 4; i++) {
        const int m = m0 + ty * 4 + i;
        float* crow = g_Wh + (size_t)m * 128 + tx * 8;
        *(float4*)(crow + 0) = make_float4(acc[i][0], acc[i][1], acc[i][2], acc[i][3]);
        *(float4*)(crow + 4) = make_float4(acc[i][4], acc[i][5], acc[i][6], acc[i][7]);
        float p1 = 0.f, p2 = 0.f;
#pragma unroll
        for (int j = 0; j < 8; j++) {
            p1 = fmaf(acc[i][j], sa[tx * 8 + j], p1);
            p2 = fmaf(acc[i][j], sa[128 + tx * 8 + j], p2);
        }
#pragma unroll
        for (int o = 8; o; o >>= 1) {
            p1 += __shfl_down_sync(0xFFFFFFFFu, p1, o, 16);
            p2 += __shfl_down_sync(0xFFFFFFFFu, p2, o, 16);
        }
        if (tx == 0) { g_s1[m] = p1; g_s2[m] = p2; }
    }
}

// register-resident bitonic compare-exchange via warp shuffle (j <= 16)
__device__ __forceinline__ void bshuf(float& kv, int& iv, unsigned ei, int k, int j) {
    float pk = __shfl_xor_sync(0xFFFFFFFFu, kv, j);
    int   pi = __shfl_xor_sync(0xFFFFFFFFu, iv, j);
    bool lower = ((ei & (unsigned)j) == 0u);
    bool up    = ((ei & (unsigned)k) == 0u);
    float kl = lower ? kv : pk;
    float kh = lower ? pk : kv;
    bool sw = up ? (kl > kh) : (kl < kh);
    if (sw) { kv = pk; iv = pi; }
}

// ---- Kernel 2: per-batch bitonic sort of s2 (hybrid smem/warp) + w=exp + Z suffix ----
__global__ void __launch_bounds__(1024) sort_kernel() {
    __shared__ float key[2048];
    __shared__ int   idx[2048];
    __shared__ float alt[2048];
    const int b = blockIdx.x;
    const int t = threadIdx.x;
    if (t < G2) g_flag[b * G2 + t] = 0;

    float k0 = g_s2[b * N + t];
    float k1 = g_s2[b * N + t + 1024];
    int   i0 = t, i1 = t + 1024;
#pragma unroll
    for (int k = 2; k <= 32; k <<= 1)
#pragma unroll
        for (int j = k >> 1; j; j >>= 1) {
            bshuf(k0, i0, (unsigned)t, k, j);
            bshuf(k1, i1, (unsigned)(t + 1024), k, j);
        }
    key[t] = k0; idx[t] = i0;
    key[t + 1024] = k1; idx[t + 1024] = i1;
    __syncthreads();

    for (int k = 64; k <= 2048; k <<= 1) {
        for (int j = k >> 1; j >= 32; j >>= 1) {
            int i = ((t & ~(j - 1)) << 1) | (t & (j - 1));
            int p = i | j;
            bool up = ((i & k) == 0);
            float ki = key[i], kp = key[p];
            bool sw = up ? (ki > kp) : (ki < kp);
            if (sw) {
                key[i] = kp; key[p] = ki;
                int ii = idx[i]; idx[i] = idx[p]; idx[p] = ii;
            }
            __syncthreads();
        }
        k0 = key[t]; i0 = idx[t];
        k1 = key[t + 1024]; i1 = idx[t + 1024];
#pragma unroll
        for (int j = 16; j; j >>= 1) {
            bshuf(k0, i0, (unsigned)t, k, j);
            bshuf(k1, i1, (unsigned)(t + 1024), k, j);
        }
        key[t] = k0; idx[t] = i0;
        key[t + 1024] = k1; idx[t + 1024] = i1;
        __syncthreads();
    }

    g_s2s[b * N + t] = key[t];               g_perm[b * N + t] = idx[t];
    g_s2s[b * N + t + 1024] = key[t + 1024]; g_perm[b * N + t + 1024] = idx[t + 1024];

    const float mx = key[2047];
    __syncthreads();
    float w0 = expf(key[t] - mx);
    float w1 = expf(key[t + 1024] - mx);
    g_w[b * N + t] = w0;
    g_w[b * N + t + 1024] = w1;
    key[t] = w0; key[t + 1024] = w1;
    __syncthreads();
    float* src = key; float* dst = alt;
    for (int o = 1; o < 2048; o <<= 1) {
        dst[t]        = src[t] + ((t + o < 2048) ? src[t + o] : 0.f);
        dst[t + 1024] = src[t + 1024] + ((t + 1024 + o < 2048) ? src[t + 1024 + o] : 0.f);
        __syncthreads();
        float* tmp = src; src = dst; dst = tmp;
    }
    g_Z[b * (N + 1) + t] = src[t];
    g_Z[b * (N + 1) + t + 1024] = src[t + 1024];
    if (t == 0) g_Z[b * (N + 1) + 2048] = 0.f;
}

// ---- Kernel 3: fused chunk partial + suffix lookback + suffix scan (512 blocks) ----
__global__ void __launch_bounds__(128) fused_scan_kernel() {
    const int b = blockIdx.x >> 6;
    const int g = blockIdx.x & (G2 - 1);
    const int f = threadIdx.x;
    __shared__ float rows[C2][F];
    __shared__ float sw[C2];
    __shared__ int   sp[C2];
    if (f < C2) {
        sw[f] = g_w[b * N + g * C2 + f];
        sp[f] = g_perm[b * N + g * C2 + f];
    }
    __syncthreads();
    const float* Whb = g_Wh + (size_t)b * N * 128;
    float accW = 0.f, accM = 0.f;
#pragma unroll 4
    for (int j = 0; j < C2; j++) {
        float x = Whb[(size_t)sp[j] * 128 + f];
        rows[j][f] = x;
        accW = fmaf(sw[j], x, accW);
        accM += x;
    }
    g_pw[b][g][f] = accW;
    g_pm[b][g][f] = accM;
    __syncthreads();
    __threadfence();
    if (f == 0) {
        ((volatile int*)g_flag)[blockIdx.x] = 1;
        for (int gg = g + 1; gg < G2; gg++)
            while (((volatile int*)g_flag)[(b << 6) | gg] == 0) {}
        __threadfence();
    }
    __syncthreads();
    float off = 0.f;
    for (int gg = g + 1; gg < G2; gg++) off += __ldcg(&g_pw[b][gg][f]);
    float acc = off;
    float* Sb = g_S + (size_t)(b * N + g * C2) * 128;
#pragma unroll 4
    for (int j = C2 - 1; j >= 0; j--) {
        acc = fmaf(sw[j], rows[j][f], acc);
        __stcg(&Sb[(size_t)j * 128 + f], acc);
    }
    if (g == 0) {
        float m = accM;
        for (int gg = 1; gg < G2; gg++) m += __ldcg(&g_pm[b][gg][f]);
        g_mean[b * 128 + f] = m * (1.f / 2048.f);
    }
}

// ---- Kernel 4: warp per row: 3-round lane-parallel ballot search + elu(S[k]/Z[k]) ----
__global__ void __launch_bounds__(256) out_kernel(float* __restrict__ out) {
    const int warp = threadIdx.x >> 5;
    const int lane = threadIdx.x & 31;
    const int row = blockIdx.x * 8 + warp;          // 0..16383
    const int b = row >> 11;
    const float* ss = g_s2s + b * N;
    const float s1v = g_s1[row];

    // round 1: lane l probes last element of 64-wide bucket l
    bool p1 = (s1v + ss[lane * 64 + 63] > 0.f);
    unsigned m1 = __ballot_sync(0xFFFFFFFFu, p1);
    int lo;
    if (m1 == 0u) {
        lo = N;                                      // all masked
    } else {
        int bkt = __ffs(m1) - 1;
        int base = bkt * 64;
        // round 2: lane l probes ss[base + 2l + 1] -> narrow to pair
        bool p2 = (s1v + ss[base + lane * 2 + 1] > 0.f);
        unsigned m2 = __ballot_sync(0xFFFFFFFFu, p2);
        int l2 = __ffs(m2) - 1;                      // m2 != 0 guaranteed (bit 31 = round-1 probe)
        int cand = base + l2 * 2;
        // round 3: resolve the pair
        lo = (s1v + ss[cand] > 0.f) ? cand : cand + 1;
    }

    float4 v;
    if (lo == N) {
        v = ((const float4*)(g_mean + b * 128))[lane];
    } else {
        float invZ = 1.f / g_Z[b * (N + 1) + lo];
        const float4* Srow = (const float4*)(g_S + (size_t)(b * N + lo) * 128);
        float4 s = __ldcg(&Srow[lane]);
        v = make_float4(s.x * invZ, s.y * invZ, s.z * invZ, s.w * invZ);
    }
    v.x = (v.x > 0.f) ? v.x : expm1f(v.x);
    v.y = (v.y > 0.f) ? v.y : expm1f(v.y);
    v.z = (v.z > 0.f) ? v.z : expm1f(v.z);
    v.w = (v.w > 0.f) ? v.w : expm1f(v.w);
    ((float4*)(out + (size_t)row * 128))[lane] = v;
}

// ---------------- launch ----------------
extern "C" void kernel_launch(void* const* d_in, const int* in_sizes, int n_in,
                              void* d_out, int out_size) {
    const float* h = (const float*)d_in[0];   // [8,2048,128]
    const float* W = (const float*)d_in[1];   // [128,128]
    const float* a = (const float*)d_in[2];   // [256,1]
    float* out = (float*)d_out;

    gemm_kernel<<<BN / 64, 256>>>(h, W, a);
    sort_kernel<<<B, 1024>>>();
    fused_scan_kernel<<<B * G2, 128>>>();
    out_kernel<<<BN / 8, 256>>>(out);
}